// round 15
// baseline (speedup 1.0000x reference)
#include <cuda_runtime.h>
#include <cuda_bf16.h>
#include <cuda_fp16.h>
#include <mma.h>
#include <cstdint>

using namespace nvcuda;

#define NODES_MAX 50048
#define EDGES_MAX 800000
#define IN_C  128
#define HID_C 128
#define OUT_C 64

// ---------------- device scratch ----------------
__device__ __half g_hh  [(size_t)NODES_MAX * HID_C];   // x @ W1 (fp16 storage)
__device__ float  g_h2  [(size_t)NODES_MAX * OUT_C];   // relu(agg+b1) @ W2
__device__ int    g_idx_is64;

// CSR-by-dst scratch
__device__ int    g_counts [NODES_MAX];
__device__ int    g_partial[NODES_MAX];
__device__ int    g_bsum   [64];
__device__ int    g_row_off[NODES_MAX + 1];
__device__ int    g_cursor [NODES_MAX];
__device__ float2 g_csr_sw [EDGES_MAX];   // .x = src idx (int bits), .y = weight

// ---------------- bf16 split helper ----------------
__device__ __forceinline__ void split_bf16(float v, __nv_bfloat16& h, __nv_bfloat16& l) {
    h = __float2bfloat16(v);
    l = __float2bfloat16(v - __bfloat162float(h));
}

// ================= GEMM1 (wmma bf16-split): h[M,128] = x[M,128] @ W1[128,128] ==========
// fp32 accumulate; epilogue converts to fp16 via smem stage.
#define G1_LDA 136
#define G1_AHI 0
#define G1_ALO (G1_AHI + 128 * G1_LDA * 2)
#define G1_BHI (G1_ALO + 128 * G1_LDA * 2)
#define G1_BLO (G1_BHI + 128 * G1_LDA * 2)
#define G1_SMEM (G1_BLO + 128 * G1_LDA * 2)

__global__ __launch_bounds__(256) void gemm1_wmma_kernel(
    const float* __restrict__ x, const float* __restrict__ W, int M)
{
    extern __shared__ char sm[];
    __nv_bfloat16* Ahi = reinterpret_cast<__nv_bfloat16*>(sm + G1_AHI);
    __nv_bfloat16* Alo = reinterpret_cast<__nv_bfloat16*>(sm + G1_ALO);
    __nv_bfloat16* Bhi = reinterpret_cast<__nv_bfloat16*>(sm + G1_BHI);
    __nv_bfloat16* Blo = reinterpret_cast<__nv_bfloat16*>(sm + G1_BLO);

    const int tid = threadIdx.x;
    const int wid = tid >> 5;
    const int rowBase = blockIdx.x * 128;

    for (int i = 0; i < 16; i++) {
        int q  = tid + i * 256;
        int r  = q >> 5;
        int c4 = q & 31;
        float4 v = make_float4(0.f, 0.f, 0.f, 0.f);
        int grow = rowBase + r;
        if (grow < M)
            v = *reinterpret_cast<const float4*>(x + (size_t)grow * IN_C + c4 * 4);
        __nv_bfloat16 h0, h1, h2, h3, l0, l1, l2, l3;
        split_bf16(v.x, h0, l0); split_bf16(v.y, h1, l1);
        split_bf16(v.z, h2, l2); split_bf16(v.w, h3, l3);
        int o = r * G1_LDA + c4 * 4;
        Ahi[o] = h0; Ahi[o + 1] = h1; Ahi[o + 2] = h2; Ahi[o + 3] = h3;
        Alo[o] = l0; Alo[o + 1] = l1; Alo[o + 2] = l2; Alo[o + 3] = l3;
    }
    for (int i = 0; i < 16; i++) {
        int q  = tid + i * 256;
        int r  = q >> 5;
        int c4 = q & 31;
        float4 v = *reinterpret_cast<const float4*>(W + (size_t)r * HID_C + c4 * 4);
        __nv_bfloat16 h0, h1, h2, h3, l0, l1, l2, l3;
        split_bf16(v.x, h0, l0); split_bf16(v.y, h1, l1);
        split_bf16(v.z, h2, l2); split_bf16(v.w, h3, l3);
        int o = r * G1_LDA + c4 * 4;
        Bhi[o] = h0; Bhi[o + 1] = h1; Bhi[o + 2] = h2; Bhi[o + 3] = h3;
        Blo[o] = l0; Blo[o + 1] = l1; Blo[o + 2] = l2; Blo[o + 3] = l3;
    }
    __syncthreads();

    const int warp_m = wid >> 2;
    const int warp_n = wid & 3;

    wmma::fragment<wmma::accumulator, 16, 16, 16, float> acc[4][2];
#pragma unroll
    for (int mi = 0; mi < 4; mi++)
#pragma unroll
        for (int ni = 0; ni < 2; ni++) wmma::fill_fragment(acc[mi][ni], 0.f);

#pragma unroll
    for (int ks = 0; ks < 8; ks++) {
        int k0 = ks * 16;
        wmma::fragment<wmma::matrix_b, 16, 16, 16, __nv_bfloat16, wmma::row_major> bh[2], bl[2];
#pragma unroll
        for (int ni = 0; ni < 2; ni++) {
            wmma::load_matrix_sync(bh[ni], Bhi + k0 * G1_LDA + warp_n * 32 + ni * 16, G1_LDA);
            wmma::load_matrix_sync(bl[ni], Blo + k0 * G1_LDA + warp_n * 32 + ni * 16, G1_LDA);
        }
#pragma unroll
        for (int mi = 0; mi < 4; mi++) {
            int r0 = warp_m * 64 + mi * 16;
            wmma::fragment<wmma::matrix_a, 16, 16, 16, __nv_bfloat16, wmma::row_major> ah, al;
            wmma::load_matrix_sync(ah, Ahi + r0 * G1_LDA + k0, G1_LDA);
            wmma::load_matrix_sync(al, Alo + r0 * G1_LDA + k0, G1_LDA);
#pragma unroll
            for (int ni = 0; ni < 2; ni++) {
                wmma::mma_sync(acc[mi][ni], ah, bh[ni], acc[mi][ni]);
                wmma::mma_sync(acc[mi][ni], ah, bl[ni], acc[mi][ni]);
                wmma::mma_sync(acc[mi][ni], al, bh[ni], acc[mi][ni]);
            }
        }
    }

    // epilogue: stage fp32 in smem (aliases A tiles), convert to fp16, write
    __syncthreads();
    float* stage = reinterpret_cast<float*>(sm);
#pragma unroll
    for (int mi = 0; mi < 4; mi++) {
#pragma unroll
        for (int ni = 0; ni < 2; ni++) {
            wmma::store_matrix_sync(stage + (warp_m * 64 + mi * 16) * 128 + warp_n * 32 + ni * 16,
                                    acc[mi][ni], 128, wmma::mem_row_major);
        }
    }
    __syncthreads();
    for (int i = 0; i < 32; i++) {
        int q  = tid + i * 256;
        int r  = q >> 6;
        int c2 = q & 63;
        float2 v = *reinterpret_cast<float2*>(stage + r * 128 + c2 * 2);
        reinterpret_cast<__half2*>(g_hh + (size_t)(rowBase + r) * HID_C)[c2] =
            __floats2half2_rn(v.x, v.y);
    }
}

// ================= FUSED gather1 + GEMM2 =================
// Block = 128 node rows. Phase 1: 8 warps gather relu(b1 + sum w*h[src]) rows
// into bf16-split A tiles (registers -> smem, no global agg). Phase 2: wmma
// gemm2 on the tile, h2[128,64] out.
#define F_LDA 136
#define F_LDB 72
#define F_AHI 0
#define F_ALO (F_AHI + 128 * F_LDA * 2)
#define F_BHI (F_ALO + 128 * F_LDA * 2)
#define F_BLO (F_BHI + 128 * F_LDB * 2)
#define F_SMEM (F_BLO + 128 * F_LDB * 2)

__global__ __launch_bounds__(256) void gather_gemm2_kernel(
    const float* __restrict__ b1, const float* __restrict__ W2, int n)
{
    extern __shared__ char sm[];
    __nv_bfloat16* Ahi = reinterpret_cast<__nv_bfloat16*>(sm + F_AHI);
    __nv_bfloat16* Alo = reinterpret_cast<__nv_bfloat16*>(sm + F_ALO);
    __nv_bfloat16* Bhi = reinterpret_cast<__nv_bfloat16*>(sm + F_BHI);
    __nv_bfloat16* Blo = reinterpret_cast<__nv_bfloat16*>(sm + F_BLO);

    const int tid  = threadIdx.x;
    const int wid  = tid >> 5;
    const int lane = tid & 31;
    const int rowBase = blockIdx.x * 128;

    // B tiles: W2[k][n] 128x64, bf16-split
    for (int i = 0; i < 8; i++) {
        int q  = tid + i * 256;
        int r  = q >> 4;
        int c4 = q & 15;
        float4 v = *reinterpret_cast<const float4*>(W2 + (size_t)r * OUT_C + c4 * 4);
        __nv_bfloat16 h0, h1, h2, h3, l0, l1, l2, l3;
        split_bf16(v.x, h0, l0); split_bf16(v.y, h1, l1);
        split_bf16(v.z, h2, l2); split_bf16(v.w, h3, l3);
        int o = r * F_LDB + c4 * 4;
        Bhi[o] = h0; Bhi[o + 1] = h1; Bhi[o + 2] = h2; Bhi[o + 3] = h3;
        Blo[o] = l0; Blo[o + 1] = l1; Blo[o + 2] = l2; Blo[o + 3] = l3;
    }

    // Phase 1: gather rows wid, wid+8, ... into A tiles (lane owns 4 channels)
    float4 bv = *(reinterpret_cast<const float4*>(b1) + lane);
    for (int rr = wid; rr < 128; rr += 8) {
        int node = rowBase + rr;
        float4 acc0 = make_float4(0.f, 0.f, 0.f, 0.f);
        float4 acc1 = make_float4(0.f, 0.f, 0.f, 0.f);
        float4 acc2 = make_float4(0.f, 0.f, 0.f, 0.f);
        float4 acc3 = make_float4(0.f, 0.f, 0.f, 0.f);
        float f0 = 0.f, f1 = 0.f, f2 = 0.f, f3 = 0.f;
        if (node < n) {
            int beg = g_row_off[node];
            int fin = g_row_off[node + 1];
#define F_LOAD(p, accv) do {                                                         \
        int _s = __float_as_int((p).x);                                              \
        float _w = (p).y;                                                            \
        uint2 _u = *(reinterpret_cast<const uint2*>(g_hh + (size_t)_s * HID_C) + lane); \
        __half2 _ha = *reinterpret_cast<__half2*>(&_u.x);                            \
        __half2 _hb = *reinterpret_cast<__half2*>(&_u.y);                            \
        float2 _fa = __half22float2(_ha);                                            \
        float2 _fb = __half22float2(_hb);                                            \
        (accv).x += _w * _fa.x; (accv).y += _w * _fa.y;                              \
        (accv).z += _w * _fb.x; (accv).w += _w * _fb.y;                              \
    } while (0)
            int j = beg;
            for (; j + 3 < fin; j += 4) {
                float2 p0 = g_csr_sw[j];
                float2 p1 = g_csr_sw[j + 1];
                float2 p2 = g_csr_sw[j + 2];
                float2 p3 = g_csr_sw[j + 3];
                F_LOAD(p0, acc0);
                F_LOAD(p1, acc1);
                F_LOAD(p2, acc2);
                F_LOAD(p3, acc3);
            }
            for (; j < fin; j++) {
                float2 p0 = g_csr_sw[j];
                F_LOAD(p0, acc0);
            }
#undef F_LOAD
            f0 = fmaxf(acc0.x + acc1.x + acc2.x + acc3.x + bv.x, 0.f);
            f1 = fmaxf(acc0.y + acc1.y + acc2.y + acc3.y + bv.y, 0.f);
            f2 = fmaxf(acc0.z + acc1.z + acc2.z + acc3.z + bv.z, 0.f);
            f3 = fmaxf(acc0.w + acc1.w + acc2.w + acc3.w + bv.w, 0.f);
        }
        __nv_bfloat16 h0, h1, h2, h3, l0, l1, l2, l3;
        split_bf16(f0, h0, l0); split_bf16(f1, h1, l1);
        split_bf16(f2, h2, l2); split_bf16(f3, h3, l3);
        int o = rr * F_LDA + lane * 4;
        Ahi[o] = h0; Ahi[o + 1] = h1; Ahi[o + 2] = h2; Ahi[o + 3] = h3;
        Alo[o] = l0; Alo[o + 1] = l1; Alo[o + 2] = l2; Alo[o + 3] = l3;
    }
    __syncthreads();

    // Phase 2: gemm2 wmma (4x2 warp grid over 128x64)
    const int warp_m = wid >> 1;
    const int warp_n = wid & 1;

    wmma::fragment<wmma::accumulator, 16, 16, 16, float> acc[2][2];
#pragma unroll
    for (int mi = 0; mi < 2; mi++)
#pragma unroll
        for (int ni = 0; ni < 2; ni++) wmma::fill_fragment(acc[mi][ni], 0.f);

#pragma unroll
    for (int ks = 0; ks < 8; ks++) {
        int k0 = ks * 16;
        wmma::fragment<wmma::matrix_b, 16, 16, 16, __nv_bfloat16, wmma::row_major> bh[2], bl[2];
#pragma unroll
        for (int ni = 0; ni < 2; ni++) {
            wmma::load_matrix_sync(bh[ni], Bhi + k0 * F_LDB + warp_n * 32 + ni * 16, F_LDB);
            wmma::load_matrix_sync(bl[ni], Blo + k0 * F_LDB + warp_n * 32 + ni * 16, F_LDB);
        }
#pragma unroll
        for (int mi = 0; mi < 2; mi++) {
            int r0 = warp_m * 32 + mi * 16;
            wmma::fragment<wmma::matrix_a, 16, 16, 16, __nv_bfloat16, wmma::row_major> ah, al;
            wmma::load_matrix_sync(ah, Ahi + r0 * F_LDA + k0, F_LDA);
            wmma::load_matrix_sync(al, Alo + r0 * F_LDA + k0, F_LDA);
#pragma unroll
            for (int ni = 0; ni < 2; ni++) {
                wmma::mma_sync(acc[mi][ni], ah, bh[ni], acc[mi][ni]);
                wmma::mma_sync(acc[mi][ni], ah, bl[ni], acc[mi][ni]);
                wmma::mma_sync(acc[mi][ni], al, bh[ni], acc[mi][ni]);
            }
        }
    }

#pragma unroll
    for (int mi = 0; mi < 2; mi++) {
        int r0 = rowBase + warp_m * 32 + mi * 16;
#pragma unroll
        for (int ni = 0; ni < 2; ni++) {
            wmma::store_matrix_sync(g_h2 + (size_t)r0 * OUT_C + warp_n * 32 + ni * 16,
                                    acc[mi][ni], OUT_C, wmma::mem_row_major);
        }
    }
}

// ---------------- zero counts + detect idx dtype (merged, proven) ----------------
__global__ void zero_detect_kernel(const int* __restrict__ ei_words, int n) {
    int i = blockIdx.x * blockDim.x + threadIdx.x;
    if (i < n) g_counts[i] = 0;
    if (blockIdx.x == 0 && threadIdx.x < 32) {
        int lane = threadIdx.x;
        int bad = 0;
        for (int k = lane; k < 1024; k += 32)
            if (ei_words[2 * k + 1] != 0) bad = 1;
        bad = __any_sync(0xffffffffu, bad);
        if (lane == 0) g_idx_is64 = bad ? 0 : 1;
    }
}

__device__ __forceinline__ void load_sd(const int* __restrict__ ei, int e, int E,
                                        int is64, int& s, int& d) {
    if (is64) { s = ei[2 * e]; d = ei[2 * E + 2 * e]; }
    else      { s = ei[e];     d = ei[E + e]; }
}
__device__ __forceinline__ int load_d(const int* __restrict__ ei, int e, int E, int is64) {
    return is64 ? ei[2 * E + 2 * e] : ei[E + e];
}

// ---------------- CSR build (R12-proven form) ----------------
__global__ void hist_kernel(const int* __restrict__ ei, int E) {
    int base = (blockIdx.x * blockDim.x + threadIdx.x) * 4;
    int is64 = g_idx_is64;
    int d0 = -1, d1 = -1, d2 = -1, d3 = -1;
    if (base + 0 < E) d0 = load_d(ei, base + 0, E, is64);
    if (base + 1 < E) d1 = load_d(ei, base + 1, E, is64);
    if (base + 2 < E) d2 = load_d(ei, base + 2, E, is64);
    if (base + 3 < E) d3 = load_d(ei, base + 3, E, is64);
    if (d0 >= 0) atomicAdd(&g_counts[d0], 1);
    if (d1 >= 0) atomicAdd(&g_counts[d1], 1);
    if (d2 >= 0) atomicAdd(&g_counts[d2], 1);
    if (d3 >= 0) atomicAdd(&g_counts[d3], 1);
}

__global__ __launch_bounds__(1024) void scan_local_kernel(int n) {
    __shared__ int sh[1024];
    int t = threadIdx.x;
    int idx = blockIdx.x * 1024 + t;
    int v = (idx < n) ? g_counts[idx] : 0;
    sh[t] = v;
    __syncthreads();
#pragma unroll
    for (int off = 1; off < 1024; off <<= 1) {
        int xv = (t >= off) ? sh[t - off] : 0;
        __syncthreads();
        sh[t] += xv;
        __syncthreads();
    }
    if (idx < n) g_partial[idx] = sh[t] - v;
    if (t == 1023) g_bsum[blockIdx.x] = sh[1023];
}

__global__ __launch_bounds__(1024) void scan_final_kernel(int n, int E) {
    __shared__ int pref_sh;
    int t = threadIdx.x;
    if (t < 32) {
        int lane = t;
        int partial = 0;
        for (int k = lane; k < (int)blockIdx.x; k += 32)
            partial += g_bsum[k];
#pragma unroll
        for (int off = 16; off > 0; off >>= 1)
            partial += __shfl_down_sync(0xffffffffu, partial, off);
        if (lane == 0) pref_sh = partial;
    }
    __syncthreads();
    int pref = pref_sh;
    int idx = blockIdx.x * 1024 + t;
    if (idx < n) {
        g_row_off[idx] = g_partial[idx] + pref;
        g_cursor[idx]  = 0;
    } else if (idx == n) {
        g_row_off[n] = E;
    }
}

__global__ void fill_kernel(const int* __restrict__ ei, const float* __restrict__ ew, int E) {
    int e = blockIdx.x * blockDim.x + threadIdx.x;
    if (e >= E) return;
    int s, d;
    load_sd(ei, e, E, g_idx_is64, s, d);
    int pos = g_row_off[d] + atomicAdd(&g_cursor[d], 1);
    g_csr_sw[pos] = make_float2(__int_as_float(s), ew[e]);
}

// ---------------- gather2: out[i] = b2 + sum_j h2[src_j], 64 ch ----------------
__global__ __launch_bounds__(256) void gather2_kernel(
    float* __restrict__ out, const float* __restrict__ b2, int n)
{
    int node = (blockIdx.x * blockDim.x + threadIdx.x) >> 5;
    int lane = threadIdx.x & 31;
    if (node >= n) return;
    int beg = g_row_off[node];
    int end = g_row_off[node + 1];

    float2 acc0 = make_float2(0.f, 0.f);
    float2 acc1 = make_float2(0.f, 0.f);
    float2 acc2 = make_float2(0.f, 0.f);
    float2 acc3 = make_float2(0.f, 0.f);
    int j = beg;
    for (; j + 3 < end; j += 4) {
        int s0 = __float_as_int(g_csr_sw[j].x);
        int s1 = __float_as_int(g_csr_sw[j + 1].x);
        int s2 = __float_as_int(g_csr_sw[j + 2].x);
        int s3 = __float_as_int(g_csr_sw[j + 3].x);
        float2 v0 = *(reinterpret_cast<const float2*>(g_h2 + (size_t)s0 * OUT_C) + lane);
        float2 v1 = *(reinterpret_cast<const float2*>(g_h2 + (size_t)s1 * OUT_C) + lane);
        float2 v2 = *(reinterpret_cast<const float2*>(g_h2 + (size_t)s2 * OUT_C) + lane);
        float2 v3 = *(reinterpret_cast<const float2*>(g_h2 + (size_t)s3 * OUT_C) + lane);
        acc0.x += v0.x; acc0.y += v0.y;
        acc1.x += v1.x; acc1.y += v1.y;
        acc2.x += v2.x; acc2.y += v2.y;
        acc3.x += v3.x; acc3.y += v3.y;
    }
    for (; j < end; j++) {
        int s0 = __float_as_int(g_csr_sw[j].x);
        float2 v0 = *(reinterpret_cast<const float2*>(g_h2 + (size_t)s0 * OUT_C) + lane);
        acc0.x += v0.x; acc0.y += v0.y;
    }
    float2 bv = *(reinterpret_cast<const float2*>(b2) + lane);
    acc0.x += acc1.x + acc2.x + acc3.x + bv.x;
    acc0.y += acc1.y + acc2.y + acc3.y + bv.y;
    *(reinterpret_cast<float2*>(out + (size_t)node * OUT_C) + lane) = acc0;
}

// ---------------- launch ----------------
extern "C" void kernel_launch(void* const* d_in, const int* in_sizes, int n_in,
                              void* d_out, int out_size)
{
    const float* x   = (const float*)d_in[0];
    const int*   ei  = (const int*)d_in[1];
    const float* ew  = (const float*)d_in[2];
    const float* W1  = (const float*)d_in[3];
    const float* b1  = (const float*)d_in[4];
    const float* W2  = (const float*)d_in[5];
    const float* b2  = (const float*)d_in[6];
    float*       out = (float*)d_out;

    const int N = in_sizes[0] / IN_C;
    const int E = in_sizes[2];
    const int nScanBlocks = (N + 1023) / 1024;
    const int nGemmBlocks = (N + 127) / 128;

    static cudaStream_t s_side = nullptr;
    static cudaEvent_t  s_fork = nullptr, s_join = nullptr;
    if (s_side == nullptr) {
        cudaStreamCreateWithFlags(&s_side, cudaStreamNonBlocking);
        cudaEventCreateWithFlags(&s_fork, cudaEventDisableTiming);
        cudaEventCreateWithFlags(&s_join, cudaEventDisableTiming);
        cudaFuncSetAttribute(gemm1_wmma_kernel,
                             cudaFuncAttributeMaxDynamicSharedMemorySize, G1_SMEM);
        cudaFuncSetAttribute(gather_gemm2_kernel,
                             cudaFuncAttributeMaxDynamicSharedMemorySize, F_SMEM);
    }

    // main: zero counts + detect dtype
    zero_detect_kernel<<<(N + 255) / 256, 256>>>(ei, N);

    // fork: CSR build on side stream, concurrent with gemm1 on main
    cudaEventRecord(s_fork, 0);
    cudaStreamWaitEvent(s_side, s_fork, 0);

    hist_kernel<<<((E + 3) / 4 + 255) / 256, 256, 0, s_side>>>(ei, E);
    scan_local_kernel<<<nScanBlocks, 1024, 0, s_side>>>(N);
    scan_final_kernel<<<nScanBlocks + 1, 1024, 0, s_side>>>(N, E);
    fill_kernel<<<(E + 255) / 256, 256, 0, s_side>>>(ei, ew, E);
    cudaEventRecord(s_join, s_side);

    // main: tensor-core layer-1 GEMM (fp16 output)
    gemm1_wmma_kernel<<<nGemmBlocks, 256, G1_SMEM>>>(x, W1, N);

    // join
    cudaStreamWaitEvent(0, s_join, 0);

    // fused layer-1 aggregate + layer-2 GEMM
    gather_gemm2_kernel<<<nGemmBlocks, 256, F_SMEM>>>(b1, W2, N);

    gather2_kernel<<<(N * 32 + 255) / 256, 256>>>(out, b2, N);
}

// round 16
// speedup vs baseline: 1.3440x; 1.3440x over previous
#include <cuda_runtime.h>
#include <cuda_bf16.h>
#include <cuda_fp16.h>
#include <mma.h>
#include <cstdint>

using namespace nvcuda;

#define NODES_MAX 50048
#define EDGES_MAX 800000
#define IN_C  128
#define HID_C 128
#define OUT_C 64

// ---------------- device scratch ----------------
__device__ __half g_hh  [(size_t)NODES_MAX * HID_C];   // x @ W1 (fp16)
__device__ float  g_agg [(size_t)NODES_MAX * HID_C];   // relu(gather + b1); rows>=N stay 0
__device__ __half g_h2h [(size_t)NODES_MAX * OUT_C];   // agg @ W2 (fp16)
__device__ int    g_idx_is64;

// CSR-by-dst scratch
__device__ int    g_counts [NODES_MAX];
__device__ int    g_partial[NODES_MAX];
__device__ int    g_bsum   [64];
__device__ int    g_row_off[NODES_MAX + 1];
__device__ int    g_cursor [NODES_MAX];
__device__ float2 g_csr_sw [EDGES_MAX];   // .x = src idx (int bits), .y = weight

// ---------------- bf16 split helper ----------------
__device__ __forceinline__ void split_bf16(float v, __nv_bfloat16& h, __nv_bfloat16& l) {
    h = __float2bfloat16(v);
    l = __float2bfloat16(v - __bfloat162float(h));
}

// ================= GEMM1 (wmma bf16-split): h[M,128] = x[M,128] @ W1[128,128] ==========
#define G1_LDA 136
#define G1_AHI 0
#define G1_ALO (G1_AHI + 128 * G1_LDA * 2)
#define G1_BHI (G1_ALO + 128 * G1_LDA * 2)
#define G1_BLO (G1_BHI + 128 * G1_LDA * 2)
#define G1_SMEM (G1_BLO + 128 * G1_LDA * 2)

__global__ __launch_bounds__(256) void gemm1_wmma_kernel(
    const float* __restrict__ x, const float* __restrict__ W, int M)
{
    extern __shared__ char sm[];
    __nv_bfloat16* Ahi = reinterpret_cast<__nv_bfloat16*>(sm + G1_AHI);
    __nv_bfloat16* Alo = reinterpret_cast<__nv_bfloat16*>(sm + G1_ALO);
    __nv_bfloat16* Bhi = reinterpret_cast<__nv_bfloat16*>(sm + G1_BHI);
    __nv_bfloat16* Blo = reinterpret_cast<__nv_bfloat16*>(sm + G1_BLO);

    const int tid = threadIdx.x;
    const int wid = tid >> 5;
    const int rowBase = blockIdx.x * 128;

    for (int i = 0; i < 16; i++) {
        int q  = tid + i * 256;
        int r  = q >> 5;
        int c4 = q & 31;
        float4 v = make_float4(0.f, 0.f, 0.f, 0.f);
        int grow = rowBase + r;
        if (grow < M)
            v = *reinterpret_cast<const float4*>(x + (size_t)grow * IN_C + c4 * 4);
        __nv_bfloat16 h0, h1, h2, h3, l0, l1, l2, l3;
        split_bf16(v.x, h0, l0); split_bf16(v.y, h1, l1);
        split_bf16(v.z, h2, l2); split_bf16(v.w, h3, l3);
        int o = r * G1_LDA + c4 * 4;
        Ahi[o] = h0; Ahi[o + 1] = h1; Ahi[o + 2] = h2; Ahi[o + 3] = h3;
        Alo[o] = l0; Alo[o + 1] = l1; Alo[o + 2] = l2; Alo[o + 3] = l3;
    }
    for (int i = 0; i < 16; i++) {
        int q  = tid + i * 256;
        int r  = q >> 5;
        int c4 = q & 31;
        float4 v = *reinterpret_cast<const float4*>(W + (size_t)r * HID_C + c4 * 4);
        __nv_bfloat16 h0, h1, h2, h3, l0, l1, l2, l3;
        split_bf16(v.x, h0, l0); split_bf16(v.y, h1, l1);
        split_bf16(v.z, h2, l2); split_bf16(v.w, h3, l3);
        int o = r * G1_LDA + c4 * 4;
        Bhi[o] = h0; Bhi[o + 1] = h1; Bhi[o + 2] = h2; Bhi[o + 3] = h3;
        Blo[o] = l0; Blo[o + 1] = l1; Blo[o + 2] = l2; Blo[o + 3] = l3;
    }
    __syncthreads();

    const int warp_m = wid >> 2;
    const int warp_n = wid & 3;

    wmma::fragment<wmma::accumulator, 16, 16, 16, float> acc[4][2];
#pragma unroll
    for (int mi = 0; mi < 4; mi++)
#pragma unroll
        for (int ni = 0; ni < 2; ni++) wmma::fill_fragment(acc[mi][ni], 0.f);

#pragma unroll
    for (int ks = 0; ks < 8; ks++) {
        int k0 = ks * 16;
        wmma::fragment<wmma::matrix_b, 16, 16, 16, __nv_bfloat16, wmma::row_major> bh[2], bl[2];
#pragma unroll
        for (int ni = 0; ni < 2; ni++) {
            wmma::load_matrix_sync(bh[ni], Bhi + k0 * G1_LDA + warp_n * 32 + ni * 16, G1_LDA);
            wmma::load_matrix_sync(bl[ni], Blo + k0 * G1_LDA + warp_n * 32 + ni * 16, G1_LDA);
        }
#pragma unroll
        for (int mi = 0; mi < 4; mi++) {
            int r0 = warp_m * 64 + mi * 16;
            wmma::fragment<wmma::matrix_a, 16, 16, 16, __nv_bfloat16, wmma::row_major> ah, al;
            wmma::load_matrix_sync(ah, Ahi + r0 * G1_LDA + k0, G1_LDA);
            wmma::load_matrix_sync(al, Alo + r0 * G1_LDA + k0, G1_LDA);
#pragma unroll
            for (int ni = 0; ni < 2; ni++) {
                wmma::mma_sync(acc[mi][ni], ah, bh[ni], acc[mi][ni]);
                wmma::mma_sync(acc[mi][ni], ah, bl[ni], acc[mi][ni]);
                wmma::mma_sync(acc[mi][ni], al, bh[ni], acc[mi][ni]);
            }
        }
    }

    // epilogue: stage fp32 in smem (aliases A tiles), convert to fp16, write
    __syncthreads();
    float* stage = reinterpret_cast<float*>(sm);
#pragma unroll
    for (int mi = 0; mi < 4; mi++) {
#pragma unroll
        for (int ni = 0; ni < 2; ni++) {
            wmma::store_matrix_sync(stage + (warp_m * 64 + mi * 16) * 128 + warp_n * 32 + ni * 16,
                                    acc[mi][ni], 128, wmma::mem_row_major);
        }
    }
    __syncthreads();
    for (int i = 0; i < 32; i++) {
        int q  = tid + i * 256;
        int r  = q >> 6;
        int c2 = q & 63;
        float2 v = *reinterpret_cast<float2*>(stage + r * 128 + c2 * 2);
        reinterpret_cast<__half2*>(g_hh + (size_t)(rowBase + r) * HID_C)[c2] =
            __floats2half2_rn(v.x, v.y);
    }
}

// ================= GEMM2 (wmma bf16-split): h2[M,64] = agg[M,128] @ W2[128,64] =========
// fp32 accumulate; epilogue stages fp32 in smem (aliases A tiles), writes fp16.
#define G2_LDA 136
#define G2_LDB 72
#define G2_AHI 0
#define G2_ALO (G2_AHI + 128 * G2_LDA * 2)
#define G2_BHI (G2_ALO + 128 * G2_LDA * 2)
#define G2_BLO (G2_BHI + 128 * G2_LDB * 2)
#define G2_SMEM (G2_BLO + 128 * G2_LDB * 2)

__global__ __launch_bounds__(256) void gemm2_wmma_kernel(const float* __restrict__ W2)
{
    extern __shared__ char sm[];
    __nv_bfloat16* Ahi = reinterpret_cast<__nv_bfloat16*>(sm + G2_AHI);
    __nv_bfloat16* Alo = reinterpret_cast<__nv_bfloat16*>(sm + G2_ALO);
    __nv_bfloat16* Bhi = reinterpret_cast<__nv_bfloat16*>(sm + G2_BHI);
    __nv_bfloat16* Blo = reinterpret_cast<__nv_bfloat16*>(sm + G2_BLO);

    const int tid = threadIdx.x;
    const int wid = tid >> 5;
    const int rowBase = blockIdx.x * 128;

    for (int i = 0; i < 16; i++) {
        int q  = tid + i * 256;
        int r  = q >> 5;
        int c4 = q & 31;
        float4 v = *reinterpret_cast<const float4*>(g_agg + (size_t)(rowBase + r) * HID_C + c4 * 4);
        __nv_bfloat16 h0, h1, h2, h3, l0, l1, l2, l3;
        split_bf16(v.x, h0, l0); split_bf16(v.y, h1, l1);
        split_bf16(v.z, h2, l2); split_bf16(v.w, h3, l3);
        int o = r * G2_LDA + c4 * 4;
        Ahi[o] = h0; Ahi[o + 1] = h1; Ahi[o + 2] = h2; Ahi[o + 3] = h3;
        Alo[o] = l0; Alo[o + 1] = l1; Alo[o + 2] = l2; Alo[o + 3] = l3;
    }
    for (int i = 0; i < 8; i++) {
        int q  = tid + i * 256;
        int r  = q >> 4;
        int c4 = q & 15;
        float4 v = *reinterpret_cast<const float4*>(W2 + (size_t)r * OUT_C + c4 * 4);
        __nv_bfloat16 h0, h1, h2, h3, l0, l1, l2, l3;
        split_bf16(v.x, h0, l0); split_bf16(v.y, h1, l1);
        split_bf16(v.z, h2, l2); split_bf16(v.w, h3, l3);
        int o = r * G2_LDB + c4 * 4;
        Bhi[o] = h0; Bhi[o + 1] = h1; Bhi[o + 2] = h2; Bhi[o + 3] = h3;
        Blo[o] = l0; Blo[o + 1] = l1; Blo[o + 2] = l2; Blo[o + 3] = l3;
    }
    __syncthreads();

    const int warp_m = wid >> 1;
    const int warp_n = wid & 1;

    wmma::fragment<wmma::accumulator, 16, 16, 16, float> acc[2][2];
#pragma unroll
    for (int mi = 0; mi < 2; mi++)
#pragma unroll
        for (int ni = 0; ni < 2; ni++) wmma::fill_fragment(acc[mi][ni], 0.f);

#pragma unroll
    for (int ks = 0; ks < 8; ks++) {
        int k0 = ks * 16;
        wmma::fragment<wmma::matrix_b, 16, 16, 16, __nv_bfloat16, wmma::row_major> bh[2], bl[2];
#pragma unroll
        for (int ni = 0; ni < 2; ni++) {
            wmma::load_matrix_sync(bh[ni], Bhi + k0 * G2_LDB + warp_n * 32 + ni * 16, G2_LDB);
            wmma::load_matrix_sync(bl[ni], Blo + k0 * G2_LDB + warp_n * 32 + ni * 16, G2_LDB);
        }
#pragma unroll
        for (int mi = 0; mi < 2; mi++) {
            int r0 = warp_m * 32 + mi * 16;
            wmma::fragment<wmma::matrix_a, 16, 16, 16, __nv_bfloat16, wmma::row_major> ah, al;
            wmma::load_matrix_sync(ah, Ahi + r0 * G2_LDA + k0, G2_LDA);
            wmma::load_matrix_sync(al, Alo + r0 * G2_LDA + k0, G2_LDA);
#pragma unroll
            for (int ni = 0; ni < 2; ni++) {
                wmma::mma_sync(acc[mi][ni], ah, bh[ni], acc[mi][ni]);
                wmma::mma_sync(acc[mi][ni], ah, bl[ni], acc[mi][ni]);
                wmma::mma_sync(acc[mi][ni], al, bh[ni], acc[mi][ni]);
            }
        }
    }

    // epilogue: stage fp32 (128x64 = 32KB, aliases A tiles), convert to fp16
    __syncthreads();
    float* stage = reinterpret_cast<float*>(sm);   // ld = 64
#pragma unroll
    for (int mi = 0; mi < 2; mi++) {
#pragma unroll
        for (int ni = 0; ni < 2; ni++) {
            wmma::store_matrix_sync(stage + (warp_m * 32 + mi * 16) * 64 + warp_n * 32 + ni * 16,
                                    acc[mi][ni], 64, wmma::mem_row_major);
        }
    }
    __syncthreads();
    // 4096 half2 slots (128 rows x 32 half2)
    for (int i = 0; i < 16; i++) {
        int q  = tid + i * 256;
        int r  = q >> 5;          // 32 half2 per row
        int c2 = q & 31;
        float2 v = *reinterpret_cast<float2*>(stage + r * 64 + c2 * 2);
        reinterpret_cast<__half2*>(g_h2h + (size_t)(rowBase + r) * OUT_C)[c2] =
            __floats2half2_rn(v.x, v.y);
    }
}

// ---------------- zero counts + detect idx dtype ----------------
__global__ void zero_detect_kernel(const int* __restrict__ ei_words, int n) {
    int i = blockIdx.x * blockDim.x + threadIdx.x;
    if (i < n) g_counts[i] = 0;
    if (blockIdx.x == 0 && threadIdx.x < 32) {
        int lane = threadIdx.x;
        int bad = 0;
        for (int k = lane; k < 1024; k += 32)
            if (ei_words[2 * k + 1] != 0) bad = 1;
        bad = __any_sync(0xffffffffu, bad);
        if (lane == 0) g_idx_is64 = bad ? 0 : 1;
    }
}

__device__ __forceinline__ void load_sd(const int* __restrict__ ei, int e, int E,
                                        int is64, int& s, int& d) {
    if (is64) { s = ei[2 * e]; d = ei[2 * E + 2 * e]; }
    else      { s = ei[e];     d = ei[E + e]; }
}
__device__ __forceinline__ int load_d(const int* __restrict__ ei, int e, int E, int is64) {
    return is64 ? ei[2 * E + 2 * e] : ei[E + e];
}

// ---------------- CSR build (proven form) ----------------
__global__ void hist_kernel(const int* __restrict__ ei, int E) {
    int base = (blockIdx.x * blockDim.x + threadIdx.x) * 4;
    int is64 = g_idx_is64;
    int d0 = -1, d1 = -1, d2 = -1, d3 = -1;
    if (base + 0 < E) d0 = load_d(ei, base + 0, E, is64);
    if (base + 1 < E) d1 = load_d(ei, base + 1, E, is64);
    if (base + 2 < E) d2 = load_d(ei, base + 2, E, is64);
    if (base + 3 < E) d3 = load_d(ei, base + 3, E, is64);
    if (d0 >= 0) atomicAdd(&g_counts[d0], 1);
    if (d1 >= 0) atomicAdd(&g_counts[d1], 1);
    if (d2 >= 0) atomicAdd(&g_counts[d2], 1);
    if (d3 >= 0) atomicAdd(&g_counts[d3], 1);
}

__global__ __launch_bounds__(1024) void scan_local_kernel(int n) {
    __shared__ int sh[1024];
    int t = threadIdx.x;
    int idx = blockIdx.x * 1024 + t;
    int v = (idx < n) ? g_counts[idx] : 0;
    sh[t] = v;
    __syncthreads();
#pragma unroll
    for (int off = 1; off < 1024; off <<= 1) {
        int xv = (t >= off) ? sh[t - off] : 0;
        __syncthreads();
        sh[t] += xv;
        __syncthreads();
    }
    if (idx < n) g_partial[idx] = sh[t] - v;
    if (t == 1023) g_bsum[blockIdx.x] = sh[1023];
}

__global__ __launch_bounds__(1024) void scan_final_kernel(int n, int E) {
    __shared__ int pref_sh;
    int t = threadIdx.x;
    if (t < 32) {
        int lane = t;
        int partial = 0;
        for (int k = lane; k < (int)blockIdx.x; k += 32)
            partial += g_bsum[k];
#pragma unroll
        for (int off = 16; off > 0; off >>= 1)
            partial += __shfl_down_sync(0xffffffffu, partial, off);
        if (lane == 0) pref_sh = partial;
    }
    __syncthreads();
    int pref = pref_sh;
    int idx = blockIdx.x * 1024 + t;
    if (idx < n) {
        g_row_off[idx] = g_partial[idx] + pref;
        g_cursor[idx]  = 0;
    } else if (idx == n) {
        g_row_off[n] = E;
    }
}

__global__ void fill_kernel(const int* __restrict__ ei, const float* __restrict__ ew, int E) {
    int e = blockIdx.x * blockDim.x + threadIdx.x;
    if (e >= E) return;
    int s, d;
    load_sd(ei, e, E, g_idx_is64, s, d);
    int pos = g_row_off[d] + atomicAdd(&g_cursor[d], 1);
    g_csr_sw[pos] = make_float2(__int_as_float(s), ew[e]);
}

// ---------------- gather1: agg[i] = relu(b1 + sum_j w_j*h[src_j]), 128 ch (fp16 h) ----------------
__global__ __launch_bounds__(256) void gather1_kernel(const float* __restrict__ b1, int n)
{
    int node = (blockIdx.x * blockDim.x + threadIdx.x) >> 5;
    int lane = threadIdx.x & 31;
    if (node >= n) return;
    int beg = g_row_off[node];
    int fin = g_row_off[node + 1];

    float4 acc0 = make_float4(0.f, 0.f, 0.f, 0.f);
    float4 acc1 = make_float4(0.f, 0.f, 0.f, 0.f);
    float4 acc2 = make_float4(0.f, 0.f, 0.f, 0.f);
    float4 acc3 = make_float4(0.f, 0.f, 0.f, 0.f);

#define G1_LOAD(p, accv) do {                                                        \
        int _s = __float_as_int((p).x);                                              \
        float _w = (p).y;                                                            \
        uint2 _u = *(reinterpret_cast<const uint2*>(g_hh + (size_t)_s * HID_C) + lane); \
        __half2 _ha = *reinterpret_cast<__half2*>(&_u.x);                            \
        __half2 _hb = *reinterpret_cast<__half2*>(&_u.y);                            \
        float2 _fa = __half22float2(_ha);                                            \
        float2 _fb = __half22float2(_hb);                                            \
        (accv).x += _w * _fa.x; (accv).y += _w * _fa.y;                              \
        (accv).z += _w * _fb.x; (accv).w += _w * _fb.y;                              \
    } while (0)

    int j = beg;
    for (; j + 3 < fin; j += 4) {
        float2 p0 = g_csr_sw[j];
        float2 p1 = g_csr_sw[j + 1];
        float2 p2 = g_csr_sw[j + 2];
        float2 p3 = g_csr_sw[j + 3];
        G1_LOAD(p0, acc0);
        G1_LOAD(p1, acc1);
        G1_LOAD(p2, acc2);
        G1_LOAD(p3, acc3);
    }
    for (; j < fin; j++) {
        float2 p0 = g_csr_sw[j];
        G1_LOAD(p0, acc0);
    }
#undef G1_LOAD

    acc0.x += acc1.x + acc2.x + acc3.x;
    acc0.y += acc1.y + acc2.y + acc3.y;
    acc0.z += acc1.z + acc2.z + acc3.z;
    acc0.w += acc1.w + acc2.w + acc3.w;
    float4 bv = *(reinterpret_cast<const float4*>(b1) + lane);
    acc0.x = fmaxf(acc0.x + bv.x, 0.f);
    acc0.y = fmaxf(acc0.y + bv.y, 0.f);
    acc0.z = fmaxf(acc0.z + bv.z, 0.f);
    acc0.w = fmaxf(acc0.w + bv.w, 0.f);
    *(reinterpret_cast<float4*>(g_agg + (size_t)node * HID_C) + lane) = acc0;
}

// ---------------- gather2: out[i] = b2 + sum_j h2[src_j], 64 ch (fp16 h2) ----------------
// One warp per node; lane owns 2 channels (one half2 = 4 B load per edge).
__global__ __launch_bounds__(256) void gather2_kernel(
    float* __restrict__ out, const float* __restrict__ b2, int n)
{
    int node = (blockIdx.x * blockDim.x + threadIdx.x) >> 5;
    int lane = threadIdx.x & 31;
    if (node >= n) return;
    int beg = g_row_off[node];
    int end = g_row_off[node + 1];

    float2 acc0 = make_float2(0.f, 0.f);
    float2 acc1 = make_float2(0.f, 0.f);
    float2 acc2 = make_float2(0.f, 0.f);
    float2 acc3 = make_float2(0.f, 0.f);

#define G2_LOAD(jj, accv) do {                                                       \
        int _s = __float_as_int(g_csr_sw[jj].x);                                     \
        __half2 _h = *(reinterpret_cast<const __half2*>(g_h2h + (size_t)_s * OUT_C) + lane); \
        float2 _f = __half22float2(_h);                                              \
        (accv).x += _f.x; (accv).y += _f.y;                                          \
    } while (0)

    int j = beg;
    for (; j + 3 < end; j += 4) {
        G2_LOAD(j,     acc0);
        G2_LOAD(j + 1, acc1);
        G2_LOAD(j + 2, acc2);
        G2_LOAD(j + 3, acc3);
    }
    for (; j < end; j++) {
        G2_LOAD(j, acc0);
    }
#undef G2_LOAD

    float2 bv = *(reinterpret_cast<const float2*>(b2) + lane);
    acc0.x += acc1.x + acc2.x + acc3.x + bv.x;
    acc0.y += acc1.y + acc2.y + acc3.y + bv.y;
    *(reinterpret_cast<float2*>(out + (size_t)node * OUT_C) + lane) = acc0;
}

// ---------------- launch ----------------
extern "C" void kernel_launch(void* const* d_in, const int* in_sizes, int n_in,
                              void* d_out, int out_size)
{
    const float* x   = (const float*)d_in[0];
    const int*   ei  = (const int*)d_in[1];
    const float* ew  = (const float*)d_in[2];
    const float* W1  = (const float*)d_in[3];
    const float* b1  = (const float*)d_in[4];
    const float* W2  = (const float*)d_in[5];
    const float* b2  = (const float*)d_in[6];
    float*       out = (float*)d_out;

    const int N = in_sizes[0] / IN_C;
    const int E = in_sizes[2];
    const int nScanBlocks = (N + 1023) / 1024;
    const int nGemmBlocks = (N + 127) / 128;

    static cudaStream_t s_side = nullptr;
    static cudaEvent_t  s_fork = nullptr, s_join = nullptr;
    if (s_side == nullptr) {
        cudaStreamCreateWithFlags(&s_side, cudaStreamNonBlocking);
        cudaEventCreateWithFlags(&s_fork, cudaEventDisableTiming);
        cudaEventCreateWithFlags(&s_join, cudaEventDisableTiming);
        cudaFuncSetAttribute(gemm1_wmma_kernel,
                             cudaFuncAttributeMaxDynamicSharedMemorySize, G1_SMEM);
        cudaFuncSetAttribute(gemm2_wmma_kernel,
                             cudaFuncAttributeMaxDynamicSharedMemorySize, G2_SMEM);
    }

    // main: zero counts + detect dtype
    zero_detect_kernel<<<(N + 255) / 256, 256>>>(ei, N);

    // fork: CSR build on side stream, concurrent with gemm1 on main
    cudaEventRecord(s_fork, 0);
    cudaStreamWaitEvent(s_side, s_fork, 0);

    hist_kernel<<<((E + 3) / 4 + 255) / 256, 256, 0, s_side>>>(ei, E);
    scan_local_kernel<<<nScanBlocks, 1024, 0, s_side>>>(N);
    scan_final_kernel<<<nScanBlocks + 1, 1024, 0, s_side>>>(N, E);
    fill_kernel<<<(E + 255) / 256, 256, 0, s_side>>>(ei, ew, E);
    cudaEventRecord(s_join, s_side);

    // main: tensor-core layer-1 GEMM (fp16 output)
    gemm1_wmma_kernel<<<nGemmBlocks, 256, G1_SMEM>>>(x, W1, N);

    // join
    cudaStreamWaitEvent(0, s_join, 0);

    gather1_kernel<<<(N * 32 + 255) / 256, 256>>>(b1, N);
    gemm2_wmma_kernel<<<nGemmBlocks, 256, G2_SMEM>>>(W2);
    gather2_kernel<<<(N * 32 + 255) / 256, 256>>>(out, b2, N);
}

// round 17
// speedup vs baseline: 1.3489x; 1.0037x over previous
#include <cuda_runtime.h>
#include <cuda_bf16.h>
#include <cuda_fp16.h>
#include <mma.h>
#include <cstdint>

using namespace nvcuda;

#define NODES_MAX 50048
#define EDGES_MAX 800000
#define IN_C  128
#define HID_C 128
#define OUT_C 64

// ---------------- device scratch ----------------
__device__ __half g_hh  [(size_t)NODES_MAX * HID_C];   // x @ W1 (fp16)
__device__ float  g_agg [(size_t)NODES_MAX * HID_C];   // relu(gather + b1); rows>=N stay 0
__device__ __half g_h2h [(size_t)NODES_MAX * OUT_C];   // agg @ W2 (fp16)
__device__ int    g_idx_is64;

// CSR-by-dst scratch
__device__ int    g_counts [NODES_MAX];
__device__ unsigned long long g_tile[64];   // decoupled-lookback tile state
__device__ int    g_row_off[NODES_MAX + 1];
__device__ int    g_cursor [NODES_MAX];
__device__ float2 g_csr_sw [EDGES_MAX];   // .x = src idx (int bits), .y = weight

// ---------------- bf16 split helper ----------------
__device__ __forceinline__ void split_bf16(float v, __nv_bfloat16& h, __nv_bfloat16& l) {
    h = __float2bfloat16(v);
    l = __float2bfloat16(v - __bfloat162float(h));
}

// ================= GEMM1 (wmma bf16-split): h[M,128] = x[M,128] @ W1[128,128] ==========
#define G1_LDA 136
#define G1_AHI 0
#define G1_ALO (G1_AHI + 128 * G1_LDA * 2)
#define G1_BHI (G1_ALO + 128 * G1_LDA * 2)
#define G1_BLO (G1_BHI + 128 * G1_LDA * 2)
#define G1_SMEM (G1_BLO + 128 * G1_LDA * 2)

__global__ __launch_bounds__(256) void gemm1_wmma_kernel(
    const float* __restrict__ x, const float* __restrict__ W, int M)
{
    extern __shared__ char sm[];
    __nv_bfloat16* Ahi = reinterpret_cast<__nv_bfloat16*>(sm + G1_AHI);
    __nv_bfloat16* Alo = reinterpret_cast<__nv_bfloat16*>(sm + G1_ALO);
    __nv_bfloat16* Bhi = reinterpret_cast<__nv_bfloat16*>(sm + G1_BHI);
    __nv_bfloat16* Blo = reinterpret_cast<__nv_bfloat16*>(sm + G1_BLO);

    const int tid = threadIdx.x;
    const int wid = tid >> 5;
    const int rowBase = blockIdx.x * 128;

    for (int i = 0; i < 16; i++) {
        int q  = tid + i * 256;
        int r  = q >> 5;
        int c4 = q & 31;
        float4 v = make_float4(0.f, 0.f, 0.f, 0.f);
        int grow = rowBase + r;
        if (grow < M)
            v = *reinterpret_cast<const float4*>(x + (size_t)grow * IN_C + c4 * 4);
        __nv_bfloat16 h0, h1, h2, h3, l0, l1, l2, l3;
        split_bf16(v.x, h0, l0); split_bf16(v.y, h1, l1);
        split_bf16(v.z, h2, l2); split_bf16(v.w, h3, l3);
        int o = r * G1_LDA + c4 * 4;
        Ahi[o] = h0; Ahi[o + 1] = h1; Ahi[o + 2] = h2; Ahi[o + 3] = h3;
        Alo[o] = l0; Alo[o + 1] = l1; Alo[o + 2] = l2; Alo[o + 3] = l3;
    }
    for (int i = 0; i < 16; i++) {
        int q  = tid + i * 256;
        int r  = q >> 5;
        int c4 = q & 31;
        float4 v = *reinterpret_cast<const float4*>(W + (size_t)r * HID_C + c4 * 4);
        __nv_bfloat16 h0, h1, h2, h3, l0, l1, l2, l3;
        split_bf16(v.x, h0, l0); split_bf16(v.y, h1, l1);
        split_bf16(v.z, h2, l2); split_bf16(v.w, h3, l3);
        int o = r * G1_LDA + c4 * 4;
        Bhi[o] = h0; Bhi[o + 1] = h1; Bhi[o + 2] = h2; Bhi[o + 3] = h3;
        Blo[o] = l0; Blo[o + 1] = l1; Blo[o + 2] = l2; Blo[o + 3] = l3;
    }
    __syncthreads();

    const int warp_m = wid >> 2;
    const int warp_n = wid & 3;

    wmma::fragment<wmma::accumulator, 16, 16, 16, float> acc[4][2];
#pragma unroll
    for (int mi = 0; mi < 4; mi++)
#pragma unroll
        for (int ni = 0; ni < 2; ni++) wmma::fill_fragment(acc[mi][ni], 0.f);

#pragma unroll
    for (int ks = 0; ks < 8; ks++) {
        int k0 = ks * 16;
        wmma::fragment<wmma::matrix_b, 16, 16, 16, __nv_bfloat16, wmma::row_major> bh[2], bl[2];
#pragma unroll
        for (int ni = 0; ni < 2; ni++) {
            wmma::load_matrix_sync(bh[ni], Bhi + k0 * G1_LDA + warp_n * 32 + ni * 16, G1_LDA);
            wmma::load_matrix_sync(bl[ni], Blo + k0 * G1_LDA + warp_n * 32 + ni * 16, G1_LDA);
        }
#pragma unroll
        for (int mi = 0; mi < 4; mi++) {
            int r0 = warp_m * 64 + mi * 16;
            wmma::fragment<wmma::matrix_a, 16, 16, 16, __nv_bfloat16, wmma::row_major> ah, al;
            wmma::load_matrix_sync(ah, Ahi + r0 * G1_LDA + k0, G1_LDA);
            wmma::load_matrix_sync(al, Alo + r0 * G1_LDA + k0, G1_LDA);
#pragma unroll
            for (int ni = 0; ni < 2; ni++) {
                wmma::mma_sync(acc[mi][ni], ah, bh[ni], acc[mi][ni]);
                wmma::mma_sync(acc[mi][ni], ah, bl[ni], acc[mi][ni]);
                wmma::mma_sync(acc[mi][ni], al, bh[ni], acc[mi][ni]);
            }
        }
    }

    // epilogue: stage fp32 in smem (aliases A tiles), convert to fp16, write
    __syncthreads();
    float* stage = reinterpret_cast<float*>(sm);
#pragma unroll
    for (int mi = 0; mi < 4; mi++) {
#pragma unroll
        for (int ni = 0; ni < 2; ni++) {
            wmma::store_matrix_sync(stage + (warp_m * 64 + mi * 16) * 128 + warp_n * 32 + ni * 16,
                                    acc[mi][ni], 128, wmma::mem_row_major);
        }
    }
    __syncthreads();
    for (int i = 0; i < 32; i++) {
        int q  = tid + i * 256;
        int r  = q >> 6;
        int c2 = q & 63;
        float2 v = *reinterpret_cast<float2*>(stage + r * 128 + c2 * 2);
        reinterpret_cast<__half2*>(g_hh + (size_t)(rowBase + r) * HID_C)[c2] =
            __floats2half2_rn(v.x, v.y);
    }
}

// ================= GEMM2 (wmma bf16-split): h2[M,64] = agg[M,128] @ W2[128,64] =========
#define G2_LDA 136
#define G2_LDB 72
#define G2_AHI 0
#define G2_ALO (G2_AHI + 128 * G2_LDA * 2)
#define G2_BHI (G2_ALO + 128 * G2_LDA * 2)
#define G2_BLO (G2_BHI + 128 * G2_LDB * 2)
#define G2_SMEM (G2_BLO + 128 * G2_LDB * 2)

__global__ __launch_bounds__(256) void gemm2_wmma_kernel(const float* __restrict__ W2)
{
    extern __shared__ char sm[];
    __nv_bfloat16* Ahi = reinterpret_cast<__nv_bfloat16*>(sm + G2_AHI);
    __nv_bfloat16* Alo = reinterpret_cast<__nv_bfloat16*>(sm + G2_ALO);
    __nv_bfloat16* Bhi = reinterpret_cast<__nv_bfloat16*>(sm + G2_BHI);
    __nv_bfloat16* Blo = reinterpret_cast<__nv_bfloat16*>(sm + G2_BLO);

    const int tid = threadIdx.x;
    const int wid = tid >> 5;
    const int rowBase = blockIdx.x * 128;

    for (int i = 0; i < 16; i++) {
        int q  = tid + i * 256;
        int r  = q >> 5;
        int c4 = q & 31;
        float4 v = *reinterpret_cast<const float4*>(g_agg + (size_t)(rowBase + r) * HID_C + c4 * 4);
        __nv_bfloat16 h0, h1, h2, h3, l0, l1, l2, l3;
        split_bf16(v.x, h0, l0); split_bf16(v.y, h1, l1);
        split_bf16(v.z, h2, l2); split_bf16(v.w, h3, l3);
        int o = r * G2_LDA + c4 * 4;
        Ahi[o] = h0; Ahi[o + 1] = h1; Ahi[o + 2] = h2; Ahi[o + 3] = h3;
        Alo[o] = l0; Alo[o + 1] = l1; Alo[o + 2] = l2; Alo[o + 3] = l3;
    }
    for (int i = 0; i < 8; i++) {
        int q  = tid + i * 256;
        int r  = q >> 4;
        int c4 = q & 15;
        float4 v = *reinterpret_cast<const float4*>(W2 + (size_t)r * OUT_C + c4 * 4);
        __nv_bfloat16 h0, h1, h2, h3, l0, l1, l2, l3;
        split_bf16(v.x, h0, l0); split_bf16(v.y, h1, l1);
        split_bf16(v.z, h2, l2); split_bf16(v.w, h3, l3);
        int o = r * G2_LDB + c4 * 4;
        Bhi[o] = h0; Bhi[o + 1] = h1; Bhi[o + 2] = h2; Bhi[o + 3] = h3;
        Blo[o] = l0; Blo[o + 1] = l1; Blo[o + 2] = l2; Blo[o + 3] = l3;
    }
    __syncthreads();

    const int warp_m = wid >> 1;
    const int warp_n = wid & 1;

    wmma::fragment<wmma::accumulator, 16, 16, 16, float> acc[2][2];
#pragma unroll
    for (int mi = 0; mi < 2; mi++)
#pragma unroll
        for (int ni = 0; ni < 2; ni++) wmma::fill_fragment(acc[mi][ni], 0.f);

#pragma unroll
    for (int ks = 0; ks < 8; ks++) {
        int k0 = ks * 16;
        wmma::fragment<wmma::matrix_b, 16, 16, 16, __nv_bfloat16, wmma::row_major> bh[2], bl[2];
#pragma unroll
        for (int ni = 0; ni < 2; ni++) {
            wmma::load_matrix_sync(bh[ni], Bhi + k0 * G2_LDB + warp_n * 32 + ni * 16, G2_LDB);
            wmma::load_matrix_sync(bl[ni], Blo + k0 * G2_LDB + warp_n * 32 + ni * 16, G2_LDB);
        }
#pragma unroll
        for (int mi = 0; mi < 2; mi++) {
            int r0 = warp_m * 32 + mi * 16;
            wmma::fragment<wmma::matrix_a, 16, 16, 16, __nv_bfloat16, wmma::row_major> ah, al;
            wmma::load_matrix_sync(ah, Ahi + r0 * G2_LDA + k0, G2_LDA);
            wmma::load_matrix_sync(al, Alo + r0 * G2_LDA + k0, G2_LDA);
#pragma unroll
            for (int ni = 0; ni < 2; ni++) {
                wmma::mma_sync(acc[mi][ni], ah, bh[ni], acc[mi][ni]);
                wmma::mma_sync(acc[mi][ni], ah, bl[ni], acc[mi][ni]);
                wmma::mma_sync(acc[mi][ni], al, bh[ni], acc[mi][ni]);
            }
        }
    }

    // epilogue: stage fp32 (128x64 = 32KB, aliases A tiles), convert to fp16
    __syncthreads();
    float* stage = reinterpret_cast<float*>(sm);
#pragma unroll
    for (int mi = 0; mi < 2; mi++) {
#pragma unroll
        for (int ni = 0; ni < 2; ni++) {
            wmma::store_matrix_sync(stage + (warp_m * 32 + mi * 16) * 64 + warp_n * 32 + ni * 16,
                                    acc[mi][ni], 64, wmma::mem_row_major);
        }
    }
    __syncthreads();
    for (int i = 0; i < 16; i++) {
        int q  = tid + i * 256;
        int r  = q >> 5;
        int c2 = q & 31;
        float2 v = *reinterpret_cast<float2*>(stage + r * 64 + c2 * 2);
        reinterpret_cast<__half2*>(g_h2h + (size_t)(rowBase + r) * OUT_C)[c2] =
            __floats2half2_rn(v.x, v.y);
    }
}

// ---------------- zero counts + tile state + detect idx dtype ----------------
__global__ void zero_detect_kernel(const int* __restrict__ ei_words, int n) {
    int i = blockIdx.x * blockDim.x + threadIdx.x;
    if (i < n) g_counts[i] = 0;
    if (i < 64) g_tile[i] = 0ULL;
    if (blockIdx.x == 0 && threadIdx.x < 32) {
        int lane = threadIdx.x;
        int bad = 0;
        for (int k = lane; k < 1024; k += 32)
            if (ei_words[2 * k + 1] != 0) bad = 1;
        bad = __any_sync(0xffffffffu, bad);
        if (lane == 0) g_idx_is64 = bad ? 0 : 1;
    }
}

__device__ __forceinline__ void load_sd(const int* __restrict__ ei, int e, int E,
                                        int is64, int& s, int& d) {
    if (is64) { s = ei[2 * e]; d = ei[2 * E + 2 * e]; }
    else      { s = ei[e];     d = ei[E + e]; }
}
__device__ __forceinline__ int load_d(const int* __restrict__ ei, int e, int E, int is64) {
    return is64 ? ei[2 * E + 2 * e] : ei[E + e];
}

// ---------------- CSR build ----------------
__global__ void hist_kernel(const int* __restrict__ ei, int E) {
    int base = (blockIdx.x * blockDim.x + threadIdx.x) * 4;
    int is64 = g_idx_is64;
    int d0 = -1, d1 = -1, d2 = -1, d3 = -1;
    if (base + 0 < E) d0 = load_d(ei, base + 0, E, is64);
    if (base + 1 < E) d1 = load_d(ei, base + 1, E, is64);
    if (base + 2 < E) d2 = load_d(ei, base + 2, E, is64);
    if (base + 3 < E) d3 = load_d(ei, base + 3, E, is64);
    if (d0 >= 0) atomicAdd(&g_counts[d0], 1);
    if (d1 >= 0) atomicAdd(&g_counts[d1], 1);
    if (d2 >= 0) atomicAdd(&g_counts[d2], 1);
    if (d3 >= 0) atomicAdd(&g_counts[d3], 1);
}

// Single-pass exclusive scan with decoupled lookback.
// Tile state word: bit32 = published flag, low 32 bits = tile aggregate.
// Forward progress: 49 blocks <= SM count, dispatched in bid order; lookback
// waits only on lower-bid blocks.
__global__ __launch_bounds__(1024) void scan_onepass_kernel(int n, int E) {
    __shared__ int sh[1024];
    __shared__ int pref_sh;
    const int t = threadIdx.x;
    const int b = blockIdx.x;
    const int idx = b * 1024 + t;

    int v = (idx < n) ? g_counts[idx] : 0;
    sh[t] = v;
    __syncthreads();
#pragma unroll
    for (int off = 1; off < 1024; off <<= 1) {
        int xv = (t >= off) ? sh[t - off] : 0;
        __syncthreads();
        sh[t] += xv;
        __syncthreads();
    }
    int incl  = sh[t];
    int total = sh[1023];

    // publish this tile's aggregate (value carries its own flag)
    if (t == 0) {
        unsigned long long pub = (1ULL << 32) | (unsigned long long)(unsigned)total;
        atomicExch(&g_tile[b], pub);
    }

    // warp 0: lookback over predecessors, 32 at a time
    if (t < 32) {
        int lane = t;
        int pref = 0;
        for (int w = b - 1; w >= 0; w -= 32) {
            int k = w - lane;
            int part = 0;
            if (k >= 0) {
                unsigned long long val;
                do {
                    val = *(volatile unsigned long long*)&g_tile[k];
                } while (!(val >> 32));
                part = (int)(val & 0xffffffffULL);
            }
#pragma unroll
            for (int off = 16; off > 0; off >>= 1)
                part += __shfl_down_sync(0xffffffffu, part, off);
            if (lane == 0) pref += part;
        }
        if (lane == 0) pref_sh = pref;
    }
    __syncthreads();
    int pref = pref_sh;

    if (idx < n) {
        g_row_off[idx] = pref + incl - v;   // exclusive
        g_cursor[idx]  = 0;
    } else if (idx == n) {
        g_row_off[n] = E;
    }
}

__global__ void fill_kernel(const int* __restrict__ ei, const float* __restrict__ ew, int E) {
    int e = blockIdx.x * blockDim.x + threadIdx.x;
    if (e >= E) return;
    int s, d;
    load_sd(ei, e, E, g_idx_is64, s, d);
    int pos = g_row_off[d] + atomicAdd(&g_cursor[d], 1);
    g_csr_sw[pos] = make_float2(__int_as_float(s), ew[e]);
}

// ---------------- gather1: agg[i] = relu(b1 + sum_j w_j*h[src_j]), 128 ch (fp16 h) ----------------
__global__ __launch_bounds__(256) void gather1_kernel(const float* __restrict__ b1, int n)
{
    int node = (blockIdx.x * blockDim.x + threadIdx.x) >> 5;
    int lane = threadIdx.x & 31;
    if (node >= n) return;
    int beg = g_row_off[node];
    int fin = g_row_off[node + 1];

    float4 acc0 = make_float4(0.f, 0.f, 0.f, 0.f);
    float4 acc1 = make_float4(0.f, 0.f, 0.f, 0.f);
    float4 acc2 = make_float4(0.f, 0.f, 0.f, 0.f);
    float4 acc3 = make_float4(0.f, 0.f, 0.f, 0.f);

#define G1_LOAD(p, accv) do {                                                        \
        int _s = __float_as_int((p).x);                                              \
        float _w = (p).y;                                                            \
        uint2 _u = *(reinterpret_cast<const uint2*>(g_hh + (size_t)_s * HID_C) + lane); \
        __half2 _ha = *reinterpret_cast<__half2*>(&_u.x);                            \
        __half2 _hb = *reinterpret_cast<__half2*>(&_u.y);                            \
        float2 _fa = __half22float2(_ha);                                            \
        float2 _fb = __half22float2(_hb);                                            \
        (accv).x += _w * _fa.x; (accv).y += _w * _fa.y;                              \
        (accv).z += _w * _fb.x; (accv).w += _w * _fb.y;                              \
    } while (0)

    int j = beg;
    for (; j + 3 < fin; j += 4) {
        float2 p0 = g_csr_sw[j];
        float2 p1 = g_csr_sw[j + 1];
        float2 p2 = g_csr_sw[j + 2];
        float2 p3 = g_csr_sw[j + 3];
        G1_LOAD(p0, acc0);
        G1_LOAD(p1, acc1);
        G1_LOAD(p2, acc2);
        G1_LOAD(p3, acc3);
    }
    for (; j < fin; j++) {
        float2 p0 = g_csr_sw[j];
        G1_LOAD(p0, acc0);
    }
#undef G1_LOAD

    acc0.x += acc1.x + acc2.x + acc3.x;
    acc0.y += acc1.y + acc2.y + acc3.y;
    acc0.z += acc1.z + acc2.z + acc3.z;
    acc0.w += acc1.w + acc2.w + acc3.w;
    float4 bv = *(reinterpret_cast<const float4*>(b1) + lane);
    acc0.x = fmaxf(acc0.x + bv.x, 0.f);
    acc0.y = fmaxf(acc0.y + bv.y, 0.f);
    acc0.z = fmaxf(acc0.z + bv.z, 0.f);
    acc0.w = fmaxf(acc0.w + bv.w, 0.f);
    *(reinterpret_cast<float4*>(g_agg + (size_t)node * HID_C) + lane) = acc0;
}

// ---------------- gather2: out[i] = b2 + sum_j h2[src_j], 64 ch (fp16 h2) ----------------
__global__ __launch_bounds__(256) void gather2_kernel(
    float* __restrict__ out, const float* __restrict__ b2, int n)
{
    int node = (blockIdx.x * blockDim.x + threadIdx.x) >> 5;
    int lane = threadIdx.x & 31;
    if (node >= n) return;
    int beg = g_row_off[node];
    int end = g_row_off[node + 1];

    float2 acc0 = make_float2(0.f, 0.f);
    float2 acc1 = make_float2(0.f, 0.f);
    float2 acc2 = make_float2(0.f, 0.f);
    float2 acc3 = make_float2(0.f, 0.f);

#define G2_LOAD(jj, accv) do {                                                       \
        int _s = __float_as_int(g_csr_sw[jj].x);                                     \
        __half2 _h = *(reinterpret_cast<const __half2*>(g_h2h + (size_t)_s * OUT_C) + lane); \
        float2 _f = __half22float2(_h);                                              \
        (accv).x += _f.x; (accv).y += _f.y;                                          \
    } while (0)

    int j = beg;
    for (; j + 3 < end; j += 4) {
        G2_LOAD(j,     acc0);
        G2_LOAD(j + 1, acc1);
        G2_LOAD(j + 2, acc2);
        G2_LOAD(j + 3, acc3);
    }
    for (; j < end; j++) {
        G2_LOAD(j, acc0);
    }
#undef G2_LOAD

    float2 bv = *(reinterpret_cast<const float2*>(b2) + lane);
    acc0.x += acc1.x + acc2.x + acc3.x + bv.x;
    acc0.y += acc1.y + acc2.y + acc3.y + bv.y;
    *(reinterpret_cast<float2*>(out + (size_t)node * OUT_C) + lane) = acc0;
}

// ---------------- launch ----------------
extern "C" void kernel_launch(void* const* d_in, const int* in_sizes, int n_in,
                              void* d_out, int out_size)
{
    const float* x   = (const float*)d_in[0];
    const int*   ei  = (const int*)d_in[1];
    const float* ew  = (const float*)d_in[2];
    const float* W1  = (const float*)d_in[3];
    const float* b1  = (const float*)d_in[4];
    const float* W2  = (const float*)d_in[5];
    const float* b2  = (const float*)d_in[6];
    float*       out = (float*)d_out;

    const int N = in_sizes[0] / IN_C;
    const int E = in_sizes[2];
    const int nScanBlocks = (N + 1023) / 1024;
    const int nGemmBlocks = (N + 127) / 128;

    static cudaStream_t s_side = nullptr;
    static cudaEvent_t  s_fork = nullptr, s_join = nullptr;
    if (s_side == nullptr) {
        cudaStreamCreateWithFlags(&s_side, cudaStreamNonBlocking);
        cudaEventCreateWithFlags(&s_fork, cudaEventDisableTiming);
        cudaEventCreateWithFlags(&s_join, cudaEventDisableTiming);
        cudaFuncSetAttribute(gemm1_wmma_kernel,
                             cudaFuncAttributeMaxDynamicSharedMemorySize, G1_SMEM);
        cudaFuncSetAttribute(gemm2_wmma_kernel,
                             cudaFuncAttributeMaxDynamicSharedMemorySize, G2_SMEM);
    }

    // main: zero counts + tile state + detect dtype
    zero_detect_kernel<<<(N + 255) / 256, 256>>>(ei, N);

    // fork: CSR build on side stream, concurrent with gemm1 on main
    cudaEventRecord(s_fork, 0);
    cudaStreamWaitEvent(s_side, s_fork, 0);

    hist_kernel<<<((E + 3) / 4 + 255) / 256, 256, 0, s_side>>>(ei, E);
    scan_onepass_kernel<<<nScanBlocks, 1024, 0, s_side>>>(N, E);
    fill_kernel<<<(E + 255) / 256, 256, 0, s_side>>>(ei, ew, E);
    cudaEventRecord(s_join, s_side);

    // main: tensor-core layer-1 GEMM (fp16 output)
    gemm1_wmma_kernel<<<nGemmBlocks, 256, G1_SMEM>>>(x, W1, N);

    // join
    cudaStreamWaitEvent(0, s_join, 0);

    gather1_kernel<<<(N * 32 + 255) / 256, 256>>>(b1, N);
    gemm2_wmma_kernel<<<nGemmBlocks, 256, G2_SMEM>>>(W2);
    gather2_kernel<<<(N * 32 + 255) / 256, 256>>>(out, b2, N);
}